// round 2
// baseline (speedup 1.0000x reference)
#include <cuda_runtime.h>
#include <cuda_bf16.h>
#include <math.h>

// Problem constants (shape-specialized)
#define T_STEPS 128
#define NB 256
#define NC 512
#define NH 512
#define NL 26
#define NCLS 6736

// ---------------- scratch (device globals; no allocation allowed) ----------
__device__ float g_fp[(size_t)T_STEPS * NB * NH];   // feats_proj [T,B,H]  64MB
__device__ float g_hp[NB * NH];                     // h @ W_h2h^T + b
__device__ float g_gh[NB * 3 * NH];                 // h @ W_hh^T + b_hh
__device__ float g_gi[NB * 3 * NH];                 // ctx @ W_ih^T + b_ih
__device__ float g_ctx[NB * NC];                    // attention context
__device__ float g_h[NB * NH];                      // hidden state
__device__ float g_hs[(size_t)NB * NL * NH];        // all hidden states

// ---------------- fast tanh (exp2-based, ~1e-7 rel err) --------------------
__device__ __forceinline__ float fast_tanh(float x) {
    float ax = fabsf(x);
    float e = __expf(-2.0f * ax);
    float r = (1.0f - e) / (1.0f + e);
    return copysignf(r, x);
}
__device__ __forceinline__ float fast_sigmoid(float x) {
    return 1.0f / (1.0f + __expf(-x));
}

// ---------------- GEMM: C[M,N] = A[M,K] * B[N,K]^T + bias ------------------
// Big tiles: BM=BN=128, BK=16, 256 threads, TM=TN=8
__global__ __launch_bounds__(256) void gemm_tn_128(
    const float* __restrict__ A, const float* __restrict__ B,
    const float* __restrict__ bias, float* __restrict__ C,
    int M, int N, int K)
{
    __shared__ __align__(16) float As[16][128 + 4];
    __shared__ __align__(16) float Bs[16][128 + 4];
    const int tid = threadIdx.x;
    const int bm = blockIdx.y * 128;
    const int bn = blockIdx.x * 128;
    const int tx = tid & 15, ty = tid >> 4;
    const int tm0 = ty * 8, tn0 = tx * 8;

    const int lr = tid >> 2;          // 0..63
    const int lc = (tid & 3) * 4;     // 0,4,8,12

    float acc[8][8];
#pragma unroll
    for (int i = 0; i < 8; i++)
#pragma unroll
        for (int j = 0; j < 8; j++) acc[i][j] = 0.0f;

    for (int k0 = 0; k0 < K; k0 += 16) {
#pragma unroll
        for (int p = 0; p < 2; p++) {
            int row = lr + p * 64;
            int gm = bm + row;
            float4 v = make_float4(0.f, 0.f, 0.f, 0.f);
            if (gm < M) v = *(const float4*)(A + (size_t)gm * K + k0 + lc);
            As[lc + 0][row] = v.x; As[lc + 1][row] = v.y;
            As[lc + 2][row] = v.z; As[lc + 3][row] = v.w;
        }
#pragma unroll
        for (int p = 0; p < 2; p++) {
            int row = lr + p * 64;
            int gn = bn + row;
            float4 v = make_float4(0.f, 0.f, 0.f, 0.f);
            if (gn < N) v = *(const float4*)(B + (size_t)gn * K + k0 + lc);
            Bs[lc + 0][row] = v.x; Bs[lc + 1][row] = v.y;
            Bs[lc + 2][row] = v.z; Bs[lc + 3][row] = v.w;
        }
        __syncthreads();
#pragma unroll
        for (int k = 0; k < 16; k++) {
            float a[8], b[8];
            float4 a0 = *(const float4*)&As[k][tm0];
            float4 a1 = *(const float4*)&As[k][tm0 + 4];
            float4 b0 = *(const float4*)&Bs[k][tn0];
            float4 b1 = *(const float4*)&Bs[k][tn0 + 4];
            a[0]=a0.x; a[1]=a0.y; a[2]=a0.z; a[3]=a0.w;
            a[4]=a1.x; a[5]=a1.y; a[6]=a1.z; a[7]=a1.w;
            b[0]=b0.x; b[1]=b0.y; b[2]=b0.z; b[3]=b0.w;
            b[4]=b1.x; b[5]=b1.y; b[6]=b1.z; b[7]=b1.w;
#pragma unroll
            for (int i = 0; i < 8; i++)
#pragma unroll
                for (int j = 0; j < 8; j++)
                    acc[i][j] = fmaf(a[i], b[j], acc[i][j]);
        }
        __syncthreads();
    }
#pragma unroll
    for (int i = 0; i < 8; i++) {
        int gm = bm + tm0 + i;
        if (gm >= M) continue;
#pragma unroll
        for (int j = 0; j < 8; j++) {
            int gn = bn + tn0 + j;
            if (gn < N)
                C[(size_t)gm * N + gn] = acc[i][j] + (bias ? bias[gn] : 0.0f);
        }
    }
}

// Small tiles: BM=BN=64, BK=16, 256 threads, TM=TN=4
__global__ __launch_bounds__(256) void gemm_tn_64(
    const float* __restrict__ A, const float* __restrict__ B,
    const float* __restrict__ bias, float* __restrict__ C,
    int M, int N, int K)
{
    __shared__ __align__(16) float As[16][64 + 4];
    __shared__ __align__(16) float Bs[16][64 + 4];
    const int tid = threadIdx.x;
    const int bm = blockIdx.y * 64;
    const int bn = blockIdx.x * 64;
    const int tx = tid & 15, ty = tid >> 4;
    const int tm0 = ty * 4, tn0 = tx * 4;
    const int lr = tid >> 2;          // 0..63
    const int lc = (tid & 3) * 4;

    float acc[4][4];
#pragma unroll
    for (int i = 0; i < 4; i++)
#pragma unroll
        for (int j = 0; j < 4; j++) acc[i][j] = 0.0f;

    for (int k0 = 0; k0 < K; k0 += 16) {
        {
            int gm = bm + lr;
            float4 v = make_float4(0.f, 0.f, 0.f, 0.f);
            if (gm < M) v = *(const float4*)(A + (size_t)gm * K + k0 + lc);
            As[lc + 0][lr] = v.x; As[lc + 1][lr] = v.y;
            As[lc + 2][lr] = v.z; As[lc + 3][lr] = v.w;
        }
        {
            int gn = bn + lr;
            float4 v = make_float4(0.f, 0.f, 0.f, 0.f);
            if (gn < N) v = *(const float4*)(B + (size_t)gn * K + k0 + lc);
            Bs[lc + 0][lr] = v.x; Bs[lc + 1][lr] = v.y;
            Bs[lc + 2][lr] = v.z; Bs[lc + 3][lr] = v.w;
        }
        __syncthreads();
#pragma unroll
        for (int k = 0; k < 16; k++) {
            float4 a4 = *(const float4*)&As[k][tm0];
            float4 b4 = *(const float4*)&Bs[k][tn0];
            float a[4] = {a4.x, a4.y, a4.z, a4.w};
            float b[4] = {b4.x, b4.y, b4.z, b4.w};
#pragma unroll
            for (int i = 0; i < 4; i++)
#pragma unroll
                for (int j = 0; j < 4; j++)
                    acc[i][j] = fmaf(a[i], b[j], acc[i][j]);
        }
        __syncthreads();
    }
#pragma unroll
    for (int i = 0; i < 4; i++) {
        int gm = bm + tm0 + i;
        if (gm >= M) continue;
#pragma unroll
        for (int j = 0; j < 4; j++) {
            int gn = bn + tn0 + j;
            if (gn < N)
                C[(size_t)gm * N + gn] = acc[i][j] + (bias ? bias[gn] : 0.0f);
        }
    }
}

// -------- attention: one block per batch b; scores+softmax+context ----------
__global__ __launch_bounds__(256) void attn_kernel(
    const float* __restrict__ fp,     // [T,B,H] feats_proj
    const float* __restrict__ hp,     // [B,H]
    const float* __restrict__ ws,     // [H] W_score row
    const float* __restrict__ feats,  // [T,B,C]
    float* __restrict__ context)      // [B,C]
{
    const int b = blockIdx.x;
    __shared__ float s_hp[NH];
    __shared__ float s_ws[NH];
    __shared__ float s_e[T_STEPS];
    __shared__ float red_max[8];
    __shared__ float red_sum[8];
    const int tid = threadIdx.x;      // 256
    const int warp = tid >> 5, lane = tid & 31;

    for (int i = tid; i < NH; i += 256) {
        s_hp[i] = hp[b * NH + i];
        s_ws[i] = ws[i];
    }
    __syncthreads();

    // scores e[t] = sum_h tanh(fp[t,b,h] + hp[b,h]) * ws[h]
    for (int t = warp; t < T_STEPS; t += 8) {
        const float* fpr = fp + ((size_t)t * NB + b) * NH;
        float sum = 0.0f;
#pragma unroll 4
        for (int h = lane; h < NH; h += 32) {
            float x = fpr[h] + s_hp[h];
            sum = fmaf(fast_tanh(x), s_ws[h], sum);
        }
#pragma unroll
        for (int o = 16; o; o >>= 1) sum += __shfl_xor_sync(0xffffffffu, sum, o);
        if (lane == 0) s_e[t] = sum;
    }
    __syncthreads();

    // softmax over T
    float v = (tid < T_STEPS) ? s_e[tid] : -INFINITY;
    float m = v;
#pragma unroll
    for (int o = 16; o; o >>= 1) m = fmaxf(m, __shfl_xor_sync(0xffffffffu, m, o));
    if (lane == 0) red_max[warp] = m;
    __syncthreads();
    float m0 = red_max[0];
#pragma unroll
    for (int w = 1; w < 8; w++) m0 = fmaxf(m0, red_max[w]);
    float ev = (tid < T_STEPS) ? __expf(v - m0) : 0.0f;
    float s = ev;
#pragma unroll
    for (int o = 16; o; o >>= 1) s += __shfl_xor_sync(0xffffffffu, s, o);
    if (lane == 0) red_sum[warp] = s;
    __syncthreads();
    float tot = 0.0f;
#pragma unroll
    for (int w = 0; w < 8; w++) tot += red_sum[w];
    if (tid < T_STEPS) s_e[tid] = ev / tot;
    __syncthreads();

    // context[c] = sum_t alpha[t] * feats[t,b,c]
    for (int c = tid; c < NC; c += 256) {
        float acc = 0.0f;
#pragma unroll 4
        for (int t = 0; t < T_STEPS; t++)
            acc = fmaf(s_e[t], feats[((size_t)t * NB + b) * NC + c], acc);
        context[b * NC + c] = acc;
    }
}

// -------- GRU gates: h_new = (1-z)*n + z*h; write into h and hs --------------
__global__ __launch_bounds__(256) void gru_kernel(
    const float* __restrict__ gi, const float* __restrict__ gh,
    float* __restrict__ h, float* __restrict__ hs, int step)
{
    int idx = blockIdx.x * 256 + threadIdx.x;
    if (idx >= NB * NH) return;
    int b = idx >> 9, hh = idx & (NH - 1);
    const float* gib = gi + b * 3 * NH;
    const float* ghb = gh + b * 3 * NH;
    float r = fast_sigmoid(gib[hh]            + ghb[hh]);
    float z = fast_sigmoid(gib[NH + hh]       + ghb[NH + hh]);
    float n = fast_tanh   (gib[2 * NH + hh] + r * ghb[2 * NH + hh]);
    float hprev = h[idx];
    float hnew = (1.0f - z) * n + z * hprev;
    h[idx] = hnew;
    hs[((size_t)b * NL + step) * NH + hh] = hnew;
}

__global__ void zero_kernel(float* p, int n) {
    int i = blockIdx.x * 256 + threadIdx.x;
    if (i < n) p[i] = 0.0f;
}

// ---------------------------------------------------------------------------
extern "C" void kernel_launch(void* const* d_in, const int* in_sizes, int n_in,
                              void* d_out, int out_size)
{
    const float* feats   = (const float*)d_in[0];
    // d_in[1] = text_length (all == 26, static)
    const float* W_i2h   = (const float*)d_in[2];
    const float* W_h2h   = (const float*)d_in[3];
    const float* b_h2h   = (const float*)d_in[4];
    const float* W_score = (const float*)d_in[5];
    const float* W_ih    = (const float*)d_in[6];
    const float* W_hh    = (const float*)d_in[7];
    const float* b_ih    = (const float*)d_in[8];
    const float* b_hh    = (const float*)d_in[9];
    const float* W_gen   = (const float*)d_in[10];
    const float* b_gen   = (const float*)d_in[11];
    float* out = (float*)d_out;

    float *fp, *hp, *gh, *gi, *ctx, *h, *hs;
    cudaGetSymbolAddress((void**)&fp,  g_fp);
    cudaGetSymbolAddress((void**)&hp,  g_hp);
    cudaGetSymbolAddress((void**)&gh,  g_gh);
    cudaGetSymbolAddress((void**)&gi,  g_gi);
    cudaGetSymbolAddress((void**)&ctx, g_ctx);
    cudaGetSymbolAddress((void**)&h,   g_h);
    cudaGetSymbolAddress((void**)&hs,  g_hs);

    // h = 0
    zero_kernel<<<(NB * NH + 255) / 256, 256>>>(h, NB * NH);

    // feats_proj = feats @ W_i2h^T   [T*B, H]
    {
        dim3 grid(NH / 128, (T_STEPS * NB) / 128);
        gemm_tn_128<<<grid, 256>>>(feats, W_i2h, nullptr, fp,
                                   T_STEPS * NB, NH, NC);
    }

    for (int step = 0; step < NL; step++) {
        // hp = h @ W_h2h^T + b_h2h   [B, H]
        {
            dim3 grid(NH / 64, NB / 64);
            gemm_tn_64<<<grid, 256>>>(h, W_h2h, b_h2h, hp, NB, NH, NH);
        }
        // gh = h @ W_hh^T + b_hh     [B, 3H]
        {
            dim3 grid(3 * NH / 64, NB / 64);
            gemm_tn_64<<<grid, 256>>>(h, W_hh, b_hh, gh, NB, 3 * NH, NH);
        }
        // attention -> context
        attn_kernel<<<NB, 256>>>(fp, hp, W_score, feats, ctx);
        // gi = ctx @ W_ih^T + b_ih   [B, 3H]
        {
            dim3 grid(3 * NH / 64, NB / 64);
            gemm_tn_64<<<grid, 256>>>(ctx, W_ih, b_ih, gi, NB, 3 * NH, NC);
        }
        // gates
        gru_kernel<<<(NB * NH + 255) / 256, 256>>>(gi, gh, h, hs, step);
    }

    // probs = hs @ W_gen^T + b_gen   [B*L, NCLS]
    {
        dim3 grid((NCLS + 127) / 128, (NB * NL) / 128);
        gemm_tn_128<<<grid, 256>>>(hs, W_gen, b_gen, out,
                                   NB * NL, NCLS, NH);
    }
}

// round 3
// speedup vs baseline: 2.6867x; 2.6867x over previous
#include <cuda_runtime.h>
#include <cuda_fp16.h>
#include <math.h>

// Problem constants (shape-specialized)
#define T_STEPS 128
#define NB 256
#define NC 512
#define NH 512
#define NL 26
#define NCLS 6736

// ---------------- scratch (device globals; no allocation allowed) ----------
__device__ float  g_fp[(size_t)T_STEPS * NB * NH];   // feats_proj fp32 (GEMM out)
__device__ __half g_fph[(size_t)T_STEPS * NB * NH];  // feats_proj fp16 cache
__device__ __half g_featsh[(size_t)T_STEPS * NB * NC]; // feats fp16 cache
__device__ float  g_Wcat[4 * NH * NH];               // [2048,512]: W_h2h ; W_hh
__device__ float  g_bcat[4 * NH];
__device__ float  g_hgh[NB * 4 * NH];                // [B,2048]: hp(512) | gh(1536)
__device__ float  g_gi[NB * 3 * NH];
__device__ float  g_ctx[NB * NC];
__device__ float  g_h[NB * NH];
__device__ float  g_hs[(size_t)NB * NL * NH];

// ---------------- fast activations ----------------------------------------
__device__ __forceinline__ float fast_tanh(float x) {
    float ax = fabsf(x);
    float e = __expf(-2.0f * ax);
    float r = __fdividef(1.0f - e, 1.0f + e);
    return copysignf(r, x);
}
__device__ __forceinline__ float fast_sigmoid(float x) {
    return __fdividef(1.0f, 1.0f + __expf(-x));
}

// ================= GEMM 128x128, BK=16, register-prefetch pipelined ========
// C[M,N] = A[M,K] @ B[N,K]^T + bias
__global__ __launch_bounds__(256) void gemm_tn_128(
    const float* __restrict__ A, const float* __restrict__ B,
    const float* __restrict__ bias, float* __restrict__ C,
    int M, int N, int K)
{
    __shared__ __align__(16) float As[16][128 + 4];
    __shared__ __align__(16) float Bs[16][128 + 4];
    const int tid = threadIdx.x;
    const int bm = blockIdx.y * 128;
    const int bn = blockIdx.x * 128;
    const int tx = tid & 15, ty = tid >> 4;
    const int tm0 = ty * 8, tn0 = tx * 8;
    const int lr = tid >> 2;          // 0..63
    const int lc = (tid & 3) * 4;     // 0,4,8,12

    float acc[8][8];
#pragma unroll
    for (int i = 0; i < 8; i++)
#pragma unroll
        for (int j = 0; j < 8; j++) acc[i][j] = 0.0f;

    float4 pa[2], pb[2];
    const int nt = K >> 4;

    // prefetch tile 0
#pragma unroll
    for (int p = 0; p < 2; p++) {
        int gm = bm + lr + p * 64;
        pa[p] = (gm < M) ? *(const float4*)(A + (size_t)gm * K + lc)
                         : make_float4(0.f, 0.f, 0.f, 0.f);
        int gn = bn + lr + p * 64;
        pb[p] = (gn < N) ? *(const float4*)(B + (size_t)gn * K + lc)
                         : make_float4(0.f, 0.f, 0.f, 0.f);
    }

    for (int kt = 0; kt < nt; kt++) {
        // store prefetched regs -> smem
#pragma unroll
        for (int p = 0; p < 2; p++) {
            int row = lr + p * 64;
            As[lc + 0][row] = pa[p].x; As[lc + 1][row] = pa[p].y;
            As[lc + 2][row] = pa[p].z; As[lc + 3][row] = pa[p].w;
            Bs[lc + 0][row] = pb[p].x; Bs[lc + 1][row] = pb[p].y;
            Bs[lc + 2][row] = pb[p].z; Bs[lc + 3][row] = pb[p].w;
        }
        __syncthreads();

        // issue next-tile loads early (latency hidden under compute)
        if (kt + 1 < nt) {
            int k0 = (kt + 1) << 4;
#pragma unroll
            for (int p = 0; p < 2; p++) {
                int gm = bm + lr + p * 64;
                pa[p] = (gm < M) ? *(const float4*)(A + (size_t)gm * K + k0 + lc)
                                 : make_float4(0.f, 0.f, 0.f, 0.f);
                int gn = bn + lr + p * 64;
                pb[p] = (gn < N) ? *(const float4*)(B + (size_t)gn * K + k0 + lc)
                                 : make_float4(0.f, 0.f, 0.f, 0.f);
            }
        }

#pragma unroll
        for (int k = 0; k < 16; k++) {
            float a[8], b[8];
            float4 a0 = *(const float4*)&As[k][tm0];
            float4 a1 = *(const float4*)&As[k][tm0 + 4];
            float4 b0 = *(const float4*)&Bs[k][tn0];
            float4 b1 = *(const float4*)&Bs[k][tn0 + 4];
            a[0]=a0.x; a[1]=a0.y; a[2]=a0.z; a[3]=a0.w;
            a[4]=a1.x; a[5]=a1.y; a[6]=a1.z; a[7]=a1.w;
            b[0]=b0.x; b[1]=b0.y; b[2]=b0.z; b[3]=b0.w;
            b[4]=b1.x; b[5]=b1.y; b[6]=b1.z; b[7]=b1.w;
#pragma unroll
            for (int i = 0; i < 8; i++)
#pragma unroll
                for (int j = 0; j < 8; j++)
                    acc[i][j] = fmaf(a[i], b[j], acc[i][j]);
        }
        __syncthreads();
    }
#pragma unroll
    for (int i = 0; i < 8; i++) {
        int gm = bm + tm0 + i;
        if (gm >= M) continue;
#pragma unroll
        for (int j = 0; j < 8; j++) {
            int gn = bn + tn0 + j;
            if (gn < N)
                C[(size_t)gm * N + gn] = acc[i][j] + (bias ? bias[gn] : 0.0f);
        }
    }
}

// ================= small GEMM 64x64, BK=32, register-prefetch ==============
// exact-multiple shapes only (M%64==0, N%64==0, K%32==0)
__global__ __launch_bounds__(256) void gemm_tn_64(
    const float* __restrict__ A, const float* __restrict__ B,
    const float* __restrict__ bias, float* __restrict__ C,
    int M, int N, int K)
{
    __shared__ __align__(16) float As[32][64 + 4];
    __shared__ __align__(16) float Bs[32][64 + 4];
    const int tid = threadIdx.x;
    const int bm = blockIdx.y * 64;
    const int bn = blockIdx.x * 64;
    const int tx = tid & 15, ty = tid >> 4;
    const int tm0 = ty * 4, tn0 = tx * 4;

    float acc[4][4];
#pragma unroll
    for (int i = 0; i < 4; i++)
#pragma unroll
        for (int j = 0; j < 4; j++) acc[i][j] = 0.0f;

    float4 pa[2], pb[2];
    const int nt = K >> 5;

    // prefetch tile 0: 64x32 per matrix = 512 float4; 2 per thread
#pragma unroll
    for (int f = 0; f < 2; f++) {
        int id = tid + f * 256;
        int row = id >> 3, col = (id & 7) * 4;
        pa[f] = *(const float4*)(A + (size_t)(bm + row) * K + col);
        pb[f] = *(const float4*)(B + (size_t)(bn + row) * K + col);
    }

    for (int kt = 0; kt < nt; kt++) {
#pragma unroll
        for (int f = 0; f < 2; f++) {
            int id = tid + f * 256;
            int row = id >> 3, col = (id & 7) * 4;
            As[col + 0][row] = pa[f].x; As[col + 1][row] = pa[f].y;
            As[col + 2][row] = pa[f].z; As[col + 3][row] = pa[f].w;
            Bs[col + 0][row] = pb[f].x; Bs[col + 1][row] = pb[f].y;
            Bs[col + 2][row] = pb[f].z; Bs[col + 3][row] = pb[f].w;
        }
        __syncthreads();

        if (kt + 1 < nt) {
            int k0 = (kt + 1) << 5;
#pragma unroll
            for (int f = 0; f < 2; f++) {
                int id = tid + f * 256;
                int row = id >> 3, col = (id & 7) * 4;
                pa[f] = *(const float4*)(A + (size_t)(bm + row) * K + k0 + col);
                pb[f] = *(const float4*)(B + (size_t)(bn + row) * K + k0 + col);
            }
        }

#pragma unroll
        for (int k = 0; k < 32; k++) {
            float4 a4 = *(const float4*)&As[k][tm0];
            float4 b4 = *(const float4*)&Bs[k][tn0];
            float a[4] = {a4.x, a4.y, a4.z, a4.w};
            float b[4] = {b4.x, b4.y, b4.z, b4.w};
#pragma unroll
            for (int i = 0; i < 4; i++)
#pragma unroll
                for (int j = 0; j < 4; j++)
                    acc[i][j] = fmaf(a[i], b[j], acc[i][j]);
        }
        __syncthreads();
    }
#pragma unroll
    for (int i = 0; i < 4; i++) {
        int gm = bm + tm0 + i;
#pragma unroll
        for (int j = 0; j < 4; j++) {
            int gn = bn + tn0 + j;
            C[(size_t)gm * N + gn] = acc[i][j] + (bias ? bias[gn] : 0.0f);
        }
    }
}

// ---------- attention: block per batch; fp16 operand caches ----------------
__global__ __launch_bounds__(256) void attn_kernel(
    const __half* __restrict__ fph,    // [T,B,H]
    const float*  __restrict__ hgh,    // [B,2048]; hp = first 512 cols
    const float*  __restrict__ ws,     // [H]
    const __half* __restrict__ featsh, // [T,B,C]
    float* __restrict__ context)       // [B,C]
{
    const int b = blockIdx.x;
    __shared__ float s_hp[NH];
    __shared__ float s_ws[NH];
    __shared__ float s_e[T_STEPS];
    __shared__ float red_max[8];
    __shared__ float red_sum[8];
    const int tid = threadIdx.x;      // 256
    const int warp = tid >> 5, lane = tid & 31;

    for (int i = tid; i < NH; i += 256) {
        s_hp[i] = hgh[b * 4 * NH + i];
        s_ws[i] = ws[i];
    }
    __syncthreads();

    // scores: e[t] = sum_h tanh(fp[t,b,h] + hp[h]) * ws[h]
    for (int t = warp; t < T_STEPS; t += 8) {
        const __half2* fpr = (const __half2*)(fph + ((size_t)t * NB + b) * NH);
        float sum = 0.0f;
#pragma unroll
        for (int i = 0; i < NH / 64; i++) {     // 8 iters
            int h2 = lane + i * 32;             // half2 index
            float2 v = __half22float2(fpr[h2]);
            int h = h2 * 2;
            float t0 = fast_tanh(v.x + s_hp[h]);
            float t1 = fast_tanh(v.y + s_hp[h + 1]);
            sum = fmaf(t0, s_ws[h], sum);
            sum = fmaf(t1, s_ws[h + 1], sum);
        }
#pragma unroll
        for (int o = 16; o; o >>= 1) sum += __shfl_xor_sync(0xffffffffu, sum, o);
        if (lane == 0) s_e[t] = sum;
    }
    __syncthreads();

    // softmax over T
    float v = (tid < T_STEPS) ? s_e[tid] : -INFINITY;
    float m = v;
#pragma unroll
    for (int o = 16; o; o >>= 1) m = fmaxf(m, __shfl_xor_sync(0xffffffffu, m, o));
    if (lane == 0) red_max[warp] = m;
    __syncthreads();
    float m0 = red_max[0];
#pragma unroll
    for (int w = 1; w < 8; w++) m0 = fmaxf(m0, red_max[w]);
    float ev = (tid < T_STEPS) ? __expf(v - m0) : 0.0f;
    float s = ev;
#pragma unroll
    for (int o = 16; o; o >>= 1) s += __shfl_xor_sync(0xffffffffu, s, o);
    if (lane == 0) red_sum[warp] = s;
    __syncthreads();
    float tot = 0.0f;
#pragma unroll
    for (int w = 0; w < 8; w++) tot += red_sum[w];
    if (tid < T_STEPS) s_e[tid] = ev * __fdividef(1.0f, tot);
    __syncthreads();

    // context[c..c+1] = sum_t alpha[t] * feats[t,b,c..c+1]
    {
        int c2 = tid;                            // half2 col index (0..255)
        float acc0 = 0.0f, acc1 = 0.0f;
        const __half2* base = (const __half2*)(featsh + (size_t)b * NC) + c2;
#pragma unroll 4
        for (int t = 0; t < T_STEPS; t++) {
            float2 f2 = __half22float2(base[(size_t)t * NB * (NC / 2)]);
            float a = s_e[t];
            acc0 = fmaf(a, f2.x, acc0);
            acc1 = fmaf(a, f2.y, acc1);
        }
        context[b * NC + c2 * 2]     = acc0;
        context[b * NC + c2 * 2 + 1] = acc1;
    }
}

// ---------- GRU gates --------------------------------------------------------
__global__ __launch_bounds__(256) void gru_kernel(
    const float* __restrict__ gi, const float* __restrict__ hgh,
    float* __restrict__ h, float* __restrict__ hs, int step)
{
    int idx = blockIdx.x * 256 + threadIdx.x;
    if (idx >= NB * NH) return;
    int b = idx >> 9, hh = idx & (NH - 1);
    const float* gib = gi + b * 3 * NH;
    const float* ghb = hgh + b * 4 * NH + NH;   // gh starts after hp
    float r = fast_sigmoid(gib[hh]          + ghb[hh]);
    float z = fast_sigmoid(gib[NH + hh]     + ghb[NH + hh]);
    float n = fast_tanh   (gib[2 * NH + hh] + r * ghb[2 * NH + hh]);
    float hprev = h[idx];
    float hnew = (1.0f - z) * n + z * hprev;
    h[idx] = hnew;
    hs[((size_t)b * NL + step) * NH + hh] = hnew;
}

// ---------- setup helpers ----------------------------------------------------
__global__ void zero_kernel(float* p, int n) {
    int i = blockIdx.x * 256 + threadIdx.x;
    if (i < n) p[i] = 0.0f;
}
__global__ void concat_w_kernel(const float* __restrict__ W_h2h,
                                const float* __restrict__ W_hh,
                                const float* __restrict__ b_h2h,
                                const float* __restrict__ b_hh,
                                float* __restrict__ Wcat,
                                float* __restrict__ bcat)
{
    int i = blockIdx.x * 256 + threadIdx.x;
    int total = 4 * NH * NH;
    if (i < total) {
        int row = i / NH;
        Wcat[i] = (row < NH) ? W_h2h[i] : W_hh[i - NH * NH];
    }
    if (i < 4 * NH)
        bcat[i] = (i < NH) ? b_h2h[i] : b_hh[i - NH];
}
__global__ void f2h_kernel(const float* __restrict__ src, __half* __restrict__ dst,
                           int n2)  // n2 = n/2
{
    int i = blockIdx.x * 256 + threadIdx.x;
    if (i < n2) {
        float2 v = ((const float2*)src)[i];
        ((__half2*)dst)[i] = __floats2half2_rn(v.x, v.y);
    }
}

// ---------------------------------------------------------------------------
extern "C" void kernel_launch(void* const* d_in, const int* in_sizes, int n_in,
                              void* d_out, int out_size)
{
    const float* feats   = (const float*)d_in[0];
    const float* W_i2h   = (const float*)d_in[2];
    const float* W_h2h   = (const float*)d_in[3];
    const float* b_h2h   = (const float*)d_in[4];
    const float* W_score = (const float*)d_in[5];
    const float* W_ih    = (const float*)d_in[6];
    const float* W_hh    = (const float*)d_in[7];
    const float* b_ih    = (const float*)d_in[8];
    const float* b_hh    = (const float*)d_in[9];
    const float* W_gen   = (const float*)d_in[10];
    const float* b_gen   = (const float*)d_in[11];
    float* out = (float*)d_out;

    float *fp, *Wcat, *bcat, *hgh, *gi, *ctx, *h, *hs;
    __half *fph, *featsh;
    cudaGetSymbolAddress((void**)&fp,     g_fp);
    cudaGetSymbolAddress((void**)&fph,    g_fph);
    cudaGetSymbolAddress((void**)&featsh, g_featsh);
    cudaGetSymbolAddress((void**)&Wcat,   g_Wcat);
    cudaGetSymbolAddress((void**)&bcat,   g_bcat);
    cudaGetSymbolAddress((void**)&hgh,    g_hgh);
    cudaGetSymbolAddress((void**)&gi,     g_gi);
    cudaGetSymbolAddress((void**)&ctx,    g_ctx);
    cudaGetSymbolAddress((void**)&h,      g_h);
    cudaGetSymbolAddress((void**)&hs,     g_hs);

    zero_kernel<<<(NB * NH + 255) / 256, 256>>>(h, NB * NH);
    concat_w_kernel<<<(4 * NH * NH + 255) / 256, 256>>>(W_h2h, W_hh, b_h2h, b_hh,
                                                        Wcat, bcat);
    // feats fp16 cache
    {
        int n2 = T_STEPS * NB * NC / 2;
        f2h_kernel<<<(n2 + 255) / 256, 256>>>(feats, featsh, n2);
    }

    // feats_proj = feats @ W_i2h^T   [T*B, H]
    {
        dim3 grid(NH / 128, (T_STEPS * NB) / 128);
        gemm_tn_128<<<grid, 256>>>(feats, W_i2h, nullptr, fp,
                                   T_STEPS * NB, NH, NC);
    }
    // fp16 cache of feats_proj
    {
        int n2 = T_STEPS * NB * NH / 2;
        f2h_kernel<<<(n2 + 255) / 256, 256>>>(fp, fph, n2);
    }

    for (int step = 0; step < NL; step++) {
        // [hp | gh] = h @ Wcat^T + bcat   [B, 2048]
        {
            dim3 grid(4 * NH / 64, NB / 64);
            gemm_tn_64<<<grid, 256>>>(h, Wcat, bcat, hgh, NB, 4 * NH, NH);
        }
        attn_kernel<<<NB, 256>>>(fph, hgh, W_score, featsh, ctx);
        // gi = ctx @ W_ih^T + b_ih   [B, 3H]
        {
            dim3 grid(3 * NH / 64, NB / 64);
            gemm_tn_64<<<grid, 256>>>(ctx, W_ih, b_ih, gi, NB, 3 * NH, NC);
        }
        gru_kernel<<<(NB * NH + 255) / 256, 256>>>(gi, hgh, h, hs, step);
    }

    // probs = hs @ W_gen^T + b_gen   [B*L, NCLS]
    {
        dim3 grid((NCLS + 127) / 128, (NB * NL) / 128);
        gemm_tn_128<<<grid, 256>>>(hs, W_gen, b_gen, out,
                                   NB * NL, NCLS, NH);
    }
}

// round 6
// speedup vs baseline: 3.3586x; 1.2501x over previous
#include <cuda_runtime.h>
#include <cuda_fp16.h>
#include <cuda_bf16.h>
#include <cstdint>
#include <cstddef>
#include <math.h>

// Problem constants (shape-specialized)
#define T_STEPS 128
#define NB 256
#define NC 512
#define NH 512
#define NL 26
#define NCLS 6736
#define KDIM 512

typedef __nv_bfloat16 bf16;

// ---------------- scratch (device globals; no allocation allowed) ----------
__device__ __align__(256) bf16  g_feats_h[(size_t)T_STEPS * NB * NC];
__device__ __align__(256) bf16  g_feats_l[(size_t)T_STEPS * NB * NC];
__device__ __align__(256) __half g_fph[(size_t)T_STEPS * NB * NH];    // feats_proj fp16
__device__ __align__(256) __half g_featsh[(size_t)T_STEPS * NB * NC]; // feats fp16
__device__ __align__(256) bf16  g_Wcat_h[4 * NH * NH];
__device__ __align__(256) bf16  g_Wcat_l[4 * NH * NH];
__device__ __align__(256) float g_bcat[4 * NH];
__device__ __align__(256) bf16  g_Wih_h[3 * NH * NC];
__device__ __align__(256) bf16  g_Wih_l[3 * NH * NC];
__device__ __align__(256) bf16  g_Wi2h_h[NH * NC];
__device__ __align__(256) bf16  g_Wi2h_l[NH * NC];
__device__ __align__(256) bf16  g_Wgen_h[(size_t)NCLS * NH];
__device__ __align__(256) bf16  g_Wgen_l[(size_t)NCLS * NH];
__device__ __align__(256) float g_hgh[NB * 4 * NH];     // [B,2048]: hp | gh
__device__ __align__(256) float g_gi[NB * 3 * NH];
__device__ __align__(256) bf16  g_ctx_h[NB * NC];
__device__ __align__(256) bf16  g_ctx_l[NB * NC];
__device__ __align__(256) float g_h[NB * NH];
__device__ __align__(256) bf16  g_h_h[NB * NH];
__device__ __align__(256) bf16  g_h_l[NB * NH];
__device__ __align__(256) bf16  g_hs_h[(size_t)NB * NL * NH];
__device__ __align__(256) bf16  g_hs_l[(size_t)NB * NL * NH];

// ---------------- fast activations ----------------------------------------
__device__ __forceinline__ float fast_tanh(float x) {
    float ax = fabsf(x);
    float e = __expf(-2.0f * ax);
    float r = __fdividef(1.0f - e, 1.0f + e);
    return copysignf(r, x);
}
__device__ __forceinline__ float fast_sigmoid(float x) {
    return __fdividef(1.0f, 1.0f + __expf(-x));
}
__device__ __forceinline__ void split_bf16(float x, bf16& hi, bf16& lo) {
    hi = __float2bfloat16(x);
    lo = __float2bfloat16(x - __bfloat162float(hi));
}

// ---------------- mma / ldmatrix primitives --------------------------------
__device__ __forceinline__ void ldsm4(uint32_t* r, const bf16* p) {
    uint32_t addr = (uint32_t)__cvta_generic_to_shared(p);
    asm volatile("ldmatrix.sync.aligned.m8n8.x4.shared.b16 {%0,%1,%2,%3}, [%4];"
        : "=r"(r[0]), "=r"(r[1]), "=r"(r[2]), "=r"(r[3]) : "r"(addr));
}
__device__ __forceinline__ void mma_bf16(float* d, const uint32_t* a, const uint32_t* b) {
    asm volatile(
        "mma.sync.aligned.m16n8k16.row.col.f32.bf16.bf16.f32 "
        "{%0,%1,%2,%3}, {%4,%5,%6,%7}, {%8,%9}, {%0,%1,%2,%3};\n"
        : "+f"(d[0]), "+f"(d[1]), "+f"(d[2]), "+f"(d[3])
        : "r"(a[0]), "r"(a[1]), "r"(a[2]), "r"(a[3]), "r"(b[0]), "r"(b[1]));
}

// ============= bf16-split tensor GEMM: C[M,N] = A @ B^T + bias =============
// A given as (Ah + Al), B as (Bh + Bl); computes Ah*Bh + Ah*Bl + Al*Bh.
// BM=BN=128, BK=32, 256 threads (8 warps, 2x4), warp tile 64x32.
template<bool OUT_HALF>
__global__ __launch_bounds__(256, 1) void gemm_bf16split(
    const bf16* __restrict__ Ah, const bf16* __restrict__ Al,
    const bf16* __restrict__ Bh, const bf16* __restrict__ Bl,
    const float* __restrict__ bias, void* __restrict__ Cv,
    int M, int N, int K)
{
    constexpr int PAD = 40;   // halves per smem row (32 data + 8 pad)
    __shared__ bf16 sA[2][128 * PAD];
    __shared__ bf16 sB[2][128 * PAD];

    const int tid = threadIdx.x;
    const int bm = blockIdx.y * 128, bn = blockIdx.x * 128;
    const int warp = tid >> 5, lane = tid & 31;
    const int wm = (warp >> 2) * 64, wn = (warp & 3) * 32;

    float acc[4][4][4];
#pragma unroll
    for (int i = 0; i < 4; i++)
#pragma unroll
        for (int j = 0; j < 4; j++)
#pragma unroll
            for (int v = 0; v < 4; v++) acc[i][j][v] = 0.0f;

    // global load assignments: 2 chunks of 8 halves per thread per matrix
    const int lid0 = tid, lid1 = tid + 256;
    const int row0 = lid0 >> 2, col0 = (lid0 & 3) * 8;
    const int row1 = lid1 >> 2, col1 = (lid1 & 3) * 8;

    uint4 pAh[2], pAl[2], pBh[2], pBl[2];

#define GLOAD(P, grow, gmax, koff) \
    (((grow) < (gmax)) ? *(const uint4*)((P) + (size_t)(grow) * K + (koff)) \
                       : make_uint4(0u, 0u, 0u, 0u))

    pAh[0] = GLOAD(Ah, bm + row0, M, col0); pAh[1] = GLOAD(Ah, bm + row1, M, col1);
    pAl[0] = GLOAD(Al, bm + row0, M, col0); pAl[1] = GLOAD(Al, bm + row1, M, col1);
    pBh[0] = GLOAD(Bh, bn + row0, N, col0); pBh[1] = GLOAD(Bh, bn + row1, N, col1);
    pBl[0] = GLOAD(Bl, bn + row0, N, col0); pBl[1] = GLOAD(Bl, bn + row1, N, col1);

    const int nk = K >> 5;
    for (int kt = 0; kt < nk; kt++) {
        const int off0 = row0 * PAD + col0, off1 = row1 * PAD + col1;
        *(uint4*)&sA[0][off0] = pAh[0]; *(uint4*)&sA[0][off1] = pAh[1];
        *(uint4*)&sA[1][off0] = pAl[0]; *(uint4*)&sA[1][off1] = pAl[1];
        *(uint4*)&sB[0][off0] = pBh[0]; *(uint4*)&sB[0][off1] = pBh[1];
        *(uint4*)&sB[1][off0] = pBl[0]; *(uint4*)&sB[1][off1] = pBl[1];
        __syncthreads();

        if (kt + 1 < nk) {
            const int k0 = (kt + 1) << 5;
            pAh[0] = GLOAD(Ah, bm + row0, M, k0 + col0); pAh[1] = GLOAD(Ah, bm + row1, M, k0 + col1);
            pAl[0] = GLOAD(Al, bm + row0, M, k0 + col0); pAl[1] = GLOAD(Al, bm + row1, M, k0 + col1);
            pBh[0] = GLOAD(Bh, bn + row0, N, k0 + col0); pBh[1] = GLOAD(Bh, bn + row1, N, k0 + col1);
            pBl[0] = GLOAD(Bl, bn + row0, N, k0 + col0); pBl[1] = GLOAD(Bl, bn + row1, N, k0 + col1);
        }

#pragma unroll
        for (int kc = 0; kc < 2; kc++) {
            uint32_t ah[4][4], al[4][4], bh[4][2], bl[4][2];
            const int acol = kc * 16 + (lane >> 4) * 8;
            const int arow = lane & 15;
#pragma unroll
            for (int mt = 0; mt < 4; mt++) {
                const int r = wm + mt * 16 + arow;
                ldsm4(ah[mt], &sA[0][r * PAD + acol]);
                ldsm4(al[mt], &sA[1][r * PAD + acol]);
            }
            const int bcol = kc * 16 + ((lane >> 3) & 1) * 8;
            const int brow = (lane & 7) + (lane >> 4) * 8;
#pragma unroll
            for (int q = 0; q < 2; q++) {
                const int r = wn + q * 16 + brow;
                uint32_t t[4];
                ldsm4(t, &sB[0][r * PAD + bcol]);
                bh[2 * q][0] = t[0]; bh[2 * q][1] = t[1];
                bh[2 * q + 1][0] = t[2]; bh[2 * q + 1][1] = t[3];
                ldsm4(t, &sB[1][r * PAD + bcol]);
                bl[2 * q][0] = t[0]; bl[2 * q][1] = t[1];
                bl[2 * q + 1][0] = t[2]; bl[2 * q + 1][1] = t[3];
            }
#pragma unroll
            for (int mt = 0; mt < 4; mt++)
#pragma unroll
                for (int nt = 0; nt < 4; nt++) {
                    mma_bf16(acc[mt][nt], ah[mt], bh[nt]);
                    mma_bf16(acc[mt][nt], ah[mt], bl[nt]);
                    mma_bf16(acc[mt][nt], al[mt], bh[nt]);
                }
        }
        __syncthreads();
    }
#undef GLOAD

    // epilogue
    const int rbase = lane >> 2, cbase = (lane & 3) * 2;
#pragma unroll
    for (int mt = 0; mt < 4; mt++) {
#pragma unroll
        for (int nt = 0; nt < 4; nt++) {
            const int gm0 = bm + wm + mt * 16 + rbase;
            const int gm1 = gm0 + 8;
            const int gn = bn + wn + nt * 8 + cbase;
            if (gn >= N) continue;
            const float b0 = bias ? bias[gn] : 0.0f;
            const float b1 = bias ? bias[gn + 1] : 0.0f;
            const float v0 = acc[mt][nt][0] + b0, v1 = acc[mt][nt][1] + b1;
            const float v2 = acc[mt][nt][2] + b0, v3 = acc[mt][nt][3] + b1;
            if (OUT_HALF) {
                __half* C = (__half*)Cv;
                if (gm0 < M) *(__half2*)(C + (size_t)gm0 * N + gn) = __floats2half2_rn(v0, v1);
                if (gm1 < M) *(__half2*)(C + (size_t)gm1 * N + gn) = __floats2half2_rn(v2, v3);
            } else {
                float* C = (float*)Cv;
                if (gm0 < M) *(float2*)(C + (size_t)gm0 * N + gn) = make_float2(v0, v1);
                if (gm1 < M) *(float2*)(C + (size_t)gm1 * N + gn) = make_float2(v2, v3);
            }
        }
    }
}

// ---------- attention: block per batch; fp16 operand caches ----------------
__global__ __launch_bounds__(256) void attn_kernel(
    const __half* __restrict__ fph,    // [T,B,H]
    const float*  __restrict__ hgh,    // [B,2048]; hp = first 512 cols
    const float*  __restrict__ ws,     // [H]
    const __half* __restrict__ featsh, // [T,B,C]
    bf16* __restrict__ ctx_h, bf16* __restrict__ ctx_l)
{
    const int b = blockIdx.x;
    __shared__ float s_hp[NH];
    __shared__ float s_ws[NH];
    __shared__ float s_e[T_STEPS];
    __shared__ float red_max[8];
    __shared__ float red_sum[8];
    const int tid = threadIdx.x;      // 256
    const int warp = tid >> 5, lane = tid & 31;

    for (int i = tid; i < NH; i += 256) {
        s_hp[i] = hgh[b * 4 * NH + i];
        s_ws[i] = ws[i];
    }
    __syncthreads();

    for (int t = warp; t < T_STEPS; t += 8) {
        const __half2* fpr = (const __half2*)(fph + ((size_t)t * NB + b) * NH);
        float sum = 0.0f;
#pragma unroll
        for (int i = 0; i < NH / 64; i++) {
            const int h2 = lane + i * 32;
            const float2 v = __half22float2(fpr[h2]);
            const int h = h2 * 2;
            const float t0 = fast_tanh(v.x + s_hp[h]);
            const float t1 = fast_tanh(v.y + s_hp[h + 1]);
            sum = fmaf(t0, s_ws[h], sum);
            sum = fmaf(t1, s_ws[h + 1], sum);
        }
#pragma unroll
        for (int o = 16; o; o >>= 1) sum += __shfl_xor_sync(0xffffffffu, sum, o);
        if (lane == 0) s_e[t] = sum;
    }
    __syncthreads();

    float v = (tid < T_STEPS) ? s_e[tid] : -INFINITY;
    float m = v;
#pragma unroll
    for (int o = 16; o; o >>= 1) m = fmaxf(m, __shfl_xor_sync(0xffffffffu, m, o));
    if (lane == 0) red_max[warp] = m;
    __syncthreads();
    float m0 = red_max[0];
#pragma unroll
    for (int w = 1; w < 8; w++) m0 = fmaxf(m0, red_max[w]);
    const float ev = (tid < T_STEPS) ? __expf(v - m0) : 0.0f;
    float s = ev;
#pragma unroll
    for (int o = 16; o; o >>= 1) s += __shfl_xor_sync(0xffffffffu, s, o);
    if (lane == 0) red_sum[warp] = s;
    __syncthreads();
    float tot = 0.0f;
#pragma unroll
    for (int w = 0; w < 8; w++) tot += red_sum[w];
    if (tid < T_STEPS) s_e[tid] = ev * __fdividef(1.0f, tot);
    __syncthreads();

    {
        const int c2 = tid;                      // half2 col index (0..255)
        float acc0 = 0.0f, acc1 = 0.0f;
        const __half2* base = (const __half2*)(featsh + (size_t)b * NC) + c2;
#pragma unroll 4
        for (int t = 0; t < T_STEPS; t++) {
            const float2 f2 = __half22float2(base[(size_t)t * NB * (NC / 2)]);
            const float a = s_e[t];
            acc0 = fmaf(a, f2.x, acc0);
            acc1 = fmaf(a, f2.y, acc1);
        }
        const int c = c2 * 2;
        bf16 h0, l0, h1, l1;
        split_bf16(acc0, h0, l0);
        split_bf16(acc1, h1, l1);
        ctx_h[b * NC + c] = h0;     ctx_h[b * NC + c + 1] = h1;
        ctx_l[b * NC + c] = l0;     ctx_l[b * NC + c + 1] = l1;
    }
}

// ---------- GRU gates: also emits bf16 splits of h ---------------------------
__global__ __launch_bounds__(256) void gru_kernel(
    const float* __restrict__ gi, const float* __restrict__ hgh,
    float* __restrict__ h, bf16* __restrict__ h_h, bf16* __restrict__ h_l,
    bf16* __restrict__ hs_h, bf16* __restrict__ hs_l, int step)
{
    const int idx = blockIdx.x * 256 + threadIdx.x;
    if (idx >= NB * NH) return;
    const int b = idx >> 9, hh = idx & (NH - 1);
    const float* gib = gi + b * 3 * NH;
    const float* ghb = hgh + b * 4 * NH + NH;
    const float r = fast_sigmoid(gib[hh]          + ghb[hh]);
    const float z = fast_sigmoid(gib[NH + hh]     + ghb[NH + hh]);
    const float n = fast_tanh   (gib[2 * NH + hh] + r * ghb[2 * NH + hh]);
    const float hprev = h[idx];
    const float hnew = (1.0f - z) * n + z * hprev;
    h[idx] = hnew;
    bf16 hi, lo;
    split_bf16(hnew, hi, lo);
    h_h[idx] = hi;
    h_l[idx] = lo;
    const size_t o = ((size_t)b * NL + step) * NH + hh;
    hs_h[o] = hi;
    hs_l[o] = lo;
}

// ---------- setup helpers ----------------------------------------------------
__global__ void zero_h_kernel(float* h, bf16* h_h, bf16* h_l) {
    const int i = blockIdx.x * 256 + threadIdx.x;
    if (i < NB * NH) {
        h[i] = 0.0f;
        h_h[i] = __float2bfloat16(0.0f);
        h_l[i] = __float2bfloat16(0.0f);
    }
}
__global__ void split_kernel(const float* __restrict__ src,
                             bf16* __restrict__ hi, bf16* __restrict__ lo, int n)
{
    const int i = blockIdx.x * 256 + threadIdx.x;
    if (i < n) {
        bf16 h, l;
        split_bf16(src[i], h, l);
        hi[i] = h; lo[i] = l;
    }
}
__global__ void concat_split_kernel(const float* __restrict__ W_h2h,
                                    const float* __restrict__ W_hh,
                                    const float* __restrict__ b_h2h,
                                    const float* __restrict__ b_hh,
                                    bf16* __restrict__ Wh, bf16* __restrict__ Wl,
                                    float* __restrict__ bcat)
{
    const int i = blockIdx.x * 256 + threadIdx.x;
    const int total = 4 * NH * NH;
    if (i < total) {
        const int row = i / NH;
        const float x = (row < NH) ? W_h2h[i] : W_hh[i - NH * NH];
        bf16 h, l;
        split_bf16(x, h, l);
        Wh[i] = h; Wl[i] = l;
    }
    if (i < 4 * NH)
        bcat[i] = (i < NH) ? b_h2h[i] : b_hh[i - NH];
}
__global__ void f2h_kernel(const float* __restrict__ src, __half* __restrict__ dst,
                           int n2)
{
    const int i = blockIdx.x * 256 + threadIdx.x;
    if (i < n2) {
        const float2 v = ((const float2*)src)[i];
        ((__half2*)dst)[i] = __floats2half2_rn(v.x, v.y);
    }
}

// ---------------------------------------------------------------------------
extern "C" void kernel_launch(void* const* d_in, const int* in_sizes, int n_in,
                              void* d_out, int out_size)
{
    const float* feats   = (const float*)d_in[0];
    const float* W_i2h   = (const float*)d_in[2];
    const float* W_h2h   = (const float*)d_in[3];
    const float* b_h2h   = (const float*)d_in[4];
    const float* W_score = (const float*)d_in[5];
    const float* W_ih    = (const float*)d_in[6];
    const float* W_hh    = (const float*)d_in[7];
    const float* b_ih    = (const float*)d_in[8];
    const float* b_hh    = (const float*)d_in[9];
    const float* W_gen   = (const float*)d_in[10];
    const float* b_gen   = (const float*)d_in[11];
    float* out = (float*)d_out;

    bf16 *feats_h = 0, *feats_l = 0, *Wcat_h = 0, *Wcat_l = 0;
    bf16 *Wih_h = 0, *Wih_l = 0, *Wi2h_h = 0, *Wi2h_l = 0;
    bf16 *Wgen_h = 0, *Wgen_l = 0, *ctx_h = 0, *ctx_l = 0;
    bf16 *h_h = 0, *h_l = 0, *hs_h = 0, *hs_l = 0;
    float *bcat = 0, *hgh = 0, *gi = 0, *h = 0;
    __half *fph = 0, *featsh = 0;
    cudaGetSymbolAddress((void**)&feats_h, g_feats_h);
    cudaGetSymbolAddress((void**)&feats_l, g_feats_l);
    cudaGetSymbolAddress((void**)&fph,     g_fph);
    cudaGetSymbolAddress((void**)&featsh,  g_featsh);
    cudaGetSymbolAddress((void**)&Wcat_h,  g_Wcat_h);
    cudaGetSymbolAddress((void**)&Wcat_l,  g_Wcat_l);
    cudaGetSymbolAddress((void**)&bcat,    g_bcat);
    cudaGetSymbolAddress((void**)&Wih_h,   g_Wih_h);
    cudaGetSymbolAddress((void**)&Wih_l,   g_Wih_l);
    cudaGetSymbolAddress((void**)&Wi2h_h,  g_Wi2h_h);
    cudaGetSymbolAddress((void**)&Wi2h_l,  g_Wi2h_l);
    cudaGetSymbolAddress((void**)&Wgen_h,  g_Wgen_h);
    cudaGetSymbolAddress((void**)&Wgen_l,  g_Wgen_l);
    cudaGetSymbolAddress((void**)&hgh,     g_hgh);
    cudaGetSymbolAddress((void**)&gi,      g_gi);
    cudaGetSymbolAddress((void**)&ctx_h,   g_ctx_h);
    cudaGetSymbolAddress((void**)&ctx_l,   g_ctx_l);
    cudaGetSymbolAddress((void**)&h,       g_h);
    cudaGetSymbolAddress((void**)&h_h,     g_h_h);
    cudaGetSymbolAddress((void**)&h_l,     g_h_l);
    cudaGetSymbolAddress((void**)&hs_h,    g_hs_h);
    cudaGetSymbolAddress((void**)&hs_l,    g_hs_l);

    // ---- setup ----
    zero_h_kernel<<<(NB * NH + 255) / 256, 256>>>(h, h_h, h_l);
    {
        const int n = T_STEPS * NB * NC;
        split_kernel<<<(n + 255) / 256, 256>>>(feats, feats_h, feats_l, n);
        f2h_kernel<<<(n / 2 + 255) / 256, 256>>>(feats, featsh, n / 2);
    }
    concat_split_kernel<<<(4 * NH * NH + 255) / 256, 256>>>(
        W_h2h, W_hh, b_h2h, b_hh, Wcat_h, Wcat_l, bcat);
    split_kernel<<<(3 * NH * NC + 255) / 256, 256>>>(W_ih, Wih_h, Wih_l, 3 * NH * NC);
    split_kernel<<<(NH * NC + 255) / 256, 256>>>(W_i2h, Wi2h_h, Wi2h_l, NH * NC);
    split_kernel<<<(NCLS * NH + 255) / 256, 256>>>(W_gen, Wgen_h, Wgen_l, NCLS * NH);

    // feats_proj (fp16 out) = feats @ W_i2h^T
    {
        dim3 grid(NH / 128, (T_STEPS * NB) / 128);
        gemm_bf16split<true><<<grid, 256>>>(feats_h, feats_l, Wi2h_h, Wi2h_l,
                                            nullptr, fph, T_STEPS * NB, NH, KDIM);
    }

    // ---- recurrence ----
    for (int step = 0; step < NL; step++) {
        {
            dim3 grid(4 * NH / 128, NB / 128);
            gemm_bf16split<false><<<grid, 256>>>(h_h, h_l, Wcat_h, Wcat_l,
                                                 bcat, hgh, NB, 4 * NH, KDIM);
        }
        attn_kernel<<<NB, 256>>>(fph, hgh, W_score, featsh, ctx_h, ctx_l);
        {
            dim3 grid(3 * NH / 128, NB / 128);
            gemm_bf16split<false><<<grid, 256>>>(ctx_h, ctx_l, Wih_h, Wih_l,
                                                 b_ih, gi, NB, 3 * NH, KDIM);
        }
        gru_kernel<<<(NB * NH + 255) / 256, 256>>>(gi, hgh, h, h_h, h_l,
                                                   hs_h, hs_l, step);
    }

    // ---- generator ----
    {
        dim3 grid((NCLS + 127) / 128, (NB * NL) / 128);
        gemm_bf16split<false><<<grid, 256>>>(hs_h, hs_l, Wgen_h, Wgen_l,
                                             b_gen, out, NB * NL, NCLS, KDIM);
    }
}

// round 7
// speedup vs baseline: 3.9930x; 1.1889x over previous
#include <cuda_runtime.h>
#include <cuda_fp16.h>
#include <cuda_bf16.h>
#include <cstdint>
#include <cstddef>
#include <math.h>

#define T_STEPS 128
#define NB 256
#define NC 512
#define NH 512
#define NL 26
#define NCLS 6736
#define KDIM 512

#define NBLK 128
#define NTHR 256
#define NSLOTS (NL * 4)

typedef __nv_bfloat16 bf16;

// ---------------- scratch (device globals) ---------------------------------
__device__ __align__(256) bf16  g_feats_h[(size_t)T_STEPS * NB * NC];
__device__ __align__(256) bf16  g_feats_l[(size_t)T_STEPS * NB * NC];
__device__ __align__(256) __half g_fph[(size_t)T_STEPS * NB * NH];
__device__ __align__(256) __half g_featsh[(size_t)T_STEPS * NB * NC];
__device__ __align__(256) bf16  g_Wcat_h[4 * NH * NH];
__device__ __align__(256) bf16  g_Wcat_l[4 * NH * NH];
__device__ __align__(256) float g_bcat[4 * NH];
__device__ __align__(256) bf16  g_Wih_h[3 * NH * NC];
__device__ __align__(256) bf16  g_Wih_l[3 * NH * NC];
__device__ __align__(256) bf16  g_Wi2h_h[NH * NC];
__device__ __align__(256) bf16  g_Wi2h_l[NH * NC];
__device__ __align__(256) bf16  g_Wgen_h[(size_t)NCLS * NH];
__device__ __align__(256) bf16  g_Wgen_l[(size_t)NCLS * NH];
__device__ __align__(256) float g_hgh[NB * 4 * NH];
__device__ __align__(256) float g_gi[NB * 3 * NH];
__device__ __align__(256) bf16  g_ctx_h[NB * NC];
__device__ __align__(256) bf16  g_ctx_l[NB * NC];
__device__ __align__(256) float g_h[NB * NH];
__device__ __align__(256) bf16  g_h_h[NB * NH];
__device__ __align__(256) bf16  g_h_l[NB * NH];
__device__ __align__(256) bf16  g_hs_h[(size_t)NB * NL * NH];
__device__ __align__(256) bf16  g_hs_l[(size_t)NB * NL * NH];
__device__ unsigned g_bar_cnt[NSLOTS];

// ---------------- fast activations -----------------------------------------
__device__ __forceinline__ float fast_tanh(float x) {
    float ax = fabsf(x);
    float e = __expf(-2.0f * ax);
    float r = __fdividef(1.0f - e, 1.0f + e);
    return copysignf(r, x);
}
__device__ __forceinline__ float fast_sigmoid(float x) {
    return __fdividef(1.0f, 1.0f + __expf(-x));
}
__device__ __forceinline__ void split_bf16(float x, bf16& hi, bf16& lo) {
    hi = __float2bfloat16(x);
    lo = __float2bfloat16(x - __bfloat162float(hi));
}

// ---------------- mma / ldmatrix primitives ---------------------------------
__device__ __forceinline__ void ldsm4(uint32_t* r, const bf16* p) {
    uint32_t addr = (uint32_t)__cvta_generic_to_shared(p);
    asm volatile("ldmatrix.sync.aligned.m8n8.x4.shared.b16 {%0,%1,%2,%3}, [%4];"
        : "=r"(r[0]), "=r"(r[1]), "=r"(r[2]), "=r"(r[3]) : "r"(addr));
}
__device__ __forceinline__ void mma_bf16(float* d, const uint32_t* a, const uint32_t* b) {
    asm volatile(
        "mma.sync.aligned.m16n8k16.row.col.f32.bf16.bf16.f32 "
        "{%0,%1,%2,%3}, {%4,%5,%6,%7}, {%8,%9}, {%0,%1,%2,%3};\n"
        : "+f"(d[0]), "+f"(d[1]), "+f"(d[2]), "+f"(d[3])
        : "r"(a[0]), "r"(a[1]), "r"(a[2]), "r"(a[3]), "r"(b[0]), "r"(b[1]));
}

// ---------------- device-wide barrier (slot counters, pre-zeroed) -----------
__device__ __forceinline__ void gbar(int slot) {
    __syncthreads();
    if (threadIdx.x == 0) {
        __threadfence();                       // release prior writes
        atomicAdd(&g_bar_cnt[slot], 1u);
        unsigned v;
        do {
            asm volatile("ld.acquire.gpu.u32 %0, [%1];"
                         : "=r"(v) : "l"(&g_bar_cnt[slot]));
            if (v >= NBLK) break;
            __nanosleep(64);
        } while (true);
    }
    __syncthreads();
}

// ============ big GEMM (128x128) for i2h + generator (unchanged math) ======
template<bool OUT_HALF>
__global__ __launch_bounds__(256, 1) void gemm_bf16split(
    const bf16* __restrict__ Ah, const bf16* __restrict__ Al,
    const bf16* __restrict__ Bh, const bf16* __restrict__ Bl,
    const float* __restrict__ bias, void* __restrict__ Cv,
    int M, int N, int K)
{
    constexpr int PAD = 40;
    __shared__ bf16 sA[2][128 * PAD];
    __shared__ bf16 sB[2][128 * PAD];

    const int tid = threadIdx.x;
    const int bm = blockIdx.y * 128, bn = blockIdx.x * 128;
    const int warp = tid >> 5, lane = tid & 31;
    const int wm = (warp >> 2) * 64, wn = (warp & 3) * 32;

    float acc[4][4][4];
#pragma unroll
    for (int i = 0; i < 4; i++)
#pragma unroll
        for (int j = 0; j < 4; j++)
#pragma unroll
            for (int v = 0; v < 4; v++) acc[i][j][v] = 0.0f;

    const int row0 = tid >> 2, col0 = (tid & 3) * 8;
    const int row1 = (tid + 256) >> 2, col1 = ((tid + 256) & 3) * 8;

    uint4 pAh[2], pAl[2], pBh[2], pBl[2];

#define GLOAD(P, grow, gmax, koff) \
    (((grow) < (gmax)) ? *(const uint4*)((P) + (size_t)(grow) * K + (koff)) \
                       : make_uint4(0u, 0u, 0u, 0u))

    pAh[0] = GLOAD(Ah, bm + row0, M, col0); pAh[1] = GLOAD(Ah, bm + row1, M, col1);
    pAl[0] = GLOAD(Al, bm + row0, M, col0); pAl[1] = GLOAD(Al, bm + row1, M, col1);
    pBh[0] = GLOAD(Bh, bn + row0, N, col0); pBh[1] = GLOAD(Bh, bn + row1, N, col1);
    pBl[0] = GLOAD(Bl, bn + row0, N, col0); pBl[1] = GLOAD(Bl, bn + row1, N, col1);

    const int nk = K >> 5;
    for (int kt = 0; kt < nk; kt++) {
        const int off0 = row0 * PAD + col0, off1 = row1 * PAD + col1;
        *(uint4*)&sA[0][off0] = pAh[0]; *(uint4*)&sA[0][off1] = pAh[1];
        *(uint4*)&sA[1][off0] = pAl[0]; *(uint4*)&sA[1][off1] = pAl[1];
        *(uint4*)&sB[0][off0] = pBh[0]; *(uint4*)&sB[0][off1] = pBh[1];
        *(uint4*)&sB[1][off0] = pBl[0]; *(uint4*)&sB[1][off1] = pBl[1];
        __syncthreads();

        if (kt + 1 < nk) {
            const int k0 = (kt + 1) << 5;
            pAh[0] = GLOAD(Ah, bm + row0, M, k0 + col0); pAh[1] = GLOAD(Ah, bm + row1, M, k0 + col1);
            pAl[0] = GLOAD(Al, bm + row0, M, k0 + col0); pAl[1] = GLOAD(Al, bm + row1, M, k0 + col1);
            pBh[0] = GLOAD(Bh, bn + row0, N, k0 + col0); pBh[1] = GLOAD(Bh, bn + row1, N, k0 + col1);
            pBl[0] = GLOAD(Bl, bn + row0, N, k0 + col0); pBl[1] = GLOAD(Bl, bn + row1, N, k0 + col1);
        }

#pragma unroll
        for (int kc = 0; kc < 2; kc++) {
            uint32_t ah[4][4], al[4][4], bh[4][2], bl[4][2];
            const int acol = kc * 16 + (lane >> 4) * 8;
            const int arow = lane & 15;
#pragma unroll
            for (int mt = 0; mt < 4; mt++) {
                const int r = wm + mt * 16 + arow;
                ldsm4(ah[mt], &sA[0][r * PAD + acol]);
                ldsm4(al[mt], &sA[1][r * PAD + acol]);
            }
            const int bcol = kc * 16 + ((lane >> 3) & 1) * 8;
            const int brow = (lane & 7) + (lane >> 4) * 8;
#pragma unroll
            for (int q = 0; q < 2; q++) {
                const int r = wn + q * 16 + brow;
                uint32_t t[4];
                ldsm4(t, &sB[0][r * PAD + bcol]);
                bh[2 * q][0] = t[0]; bh[2 * q][1] = t[1];
                bh[2 * q + 1][0] = t[2]; bh[2 * q + 1][1] = t[3];
                ldsm4(t, &sB[1][r * PAD + bcol]);
                bl[2 * q][0] = t[0]; bl[2 * q][1] = t[1];
                bl[2 * q + 1][0] = t[2]; bl[2 * q + 1][1] = t[3];
            }
#pragma unroll
            for (int mt = 0; mt < 4; mt++)
#pragma unroll
                for (int nt = 0; nt < 4; nt++) {
                    mma_bf16(acc[mt][nt], ah[mt], bh[nt]);
                    mma_bf16(acc[mt][nt], ah[mt], bl[nt]);
                    mma_bf16(acc[mt][nt], al[mt], bh[nt]);
                }
        }
        __syncthreads();
    }
#undef GLOAD

    const int rbase = lane >> 2, cbase = (lane & 3) * 2;
#pragma unroll
    for (int mt = 0; mt < 4; mt++) {
#pragma unroll
        for (int nt = 0; nt < 4; nt++) {
            const int gm0 = bm + wm + mt * 16 + rbase;
            const int gm1 = gm0 + 8;
            const int gn = bn + wn + nt * 8 + cbase;
            if (gn >= N) continue;
            const float b0 = bias ? bias[gn] : 0.0f;
            const float b1 = bias ? bias[gn + 1] : 0.0f;
            const float v0 = acc[mt][nt][0] + b0, v1 = acc[mt][nt][1] + b1;
            const float v2 = acc[mt][nt][2] + b0, v3 = acc[mt][nt][3] + b1;
            if (OUT_HALF) {
                __half* C = (__half*)Cv;
                if (gm0 < M) *(__half2*)(C + (size_t)gm0 * N + gn) = __floats2half2_rn(v0, v1);
                if (gm1 < M) *(__half2*)(C + (size_t)gm1 * N + gn) = __floats2half2_rn(v2, v3);
            } else {
                float* C = (float*)Cv;
                if (gm0 < M) *(float2*)(C + (size_t)gm0 * N + gn) = make_float2(v0, v1);
                if (gm1 < M) *(float2*)(C + (size_t)gm1 * N + gn) = make_float2(v2, v3);
            }
        }
    }
}

// ============ persistent recurrence kernel ==================================
// smem: GEMM phase needs 4 * 64*40 bf16 = 20480 B; attn overlays same space.
#define PPAD 40
#define SMEM_BYTES (4 * 64 * PPAD * 2)

struct AttnSmem {
    float hp[NH];
    float ws[NH];
    float e[T_STEPS];
    float rmax[8];
    float rsum[8];
};

// 64x64 tile GEMM phase, M rows exact, K=512. 256 threads, warp tile 32x16.
__device__ __forceinline__ void gemm_phase64(
    const bf16* __restrict__ Ah, const bf16* __restrict__ Al,
    const bf16* __restrict__ Bh, const bf16* __restrict__ Bl,
    const float* __restrict__ bias, float* __restrict__ C,
    int N, int bm, int bn, char* raw)
{
    bf16* sAh = (bf16*)raw;
    bf16* sAl = sAh + 64 * PPAD;
    bf16* sBh = sAl + 64 * PPAD;
    bf16* sBl = sBh + 64 * PPAD;

    const int tid = threadIdx.x;
    const int warp = tid >> 5, lane = tid & 31;
    const int wm = (warp & 1) * 32, wn = (warp >> 1) * 16;
    const int row = tid >> 2, col = (tid & 3) * 8;
    const size_t abase = (size_t)(bm + row) * KDIM + col;
    const size_t bbase = (size_t)(bn + row) * KDIM + col;
    const int soff = row * PPAD + col;

    float acc[2][2][4];
#pragma unroll
    for (int i = 0; i < 2; i++)
#pragma unroll
        for (int j = 0; j < 2; j++)
#pragma unroll
            for (int v = 0; v < 4; v++) acc[i][j][v] = 0.0f;

    uint4 pa0 = *(const uint4*)(Ah + abase);
    uint4 pa1 = *(const uint4*)(Al + abase);
    uint4 pb0 = *(const uint4*)(Bh + bbase);
    uint4 pb1 = *(const uint4*)(Bl + bbase);

    const int nk = KDIM / 32;
    for (int kt = 0; kt < nk; kt++) {
        *(uint4*)&sAh[soff] = pa0; *(uint4*)&sAl[soff] = pa1;
        *(uint4*)&sBh[soff] = pb0; *(uint4*)&sBl[soff] = pb1;
        __syncthreads();

        if (kt + 1 < nk) {
            const int k0 = (kt + 1) * 32;
            pa0 = *(const uint4*)(Ah + abase + k0);
            pa1 = *(const uint4*)(Al + abase + k0);
            pb0 = *(const uint4*)(Bh + bbase + k0);
            pb1 = *(const uint4*)(Bl + bbase + k0);
        }

#pragma unroll
        for (int kc = 0; kc < 2; kc++) {
            uint32_t ah[2][4], al[2][4], bh[2][2], bl[2][2];
            const int acol = kc * 16 + (lane >> 4) * 8;
            const int arow = lane & 15;
#pragma unroll
            for (int mt = 0; mt < 2; mt++) {
                const int r = wm + mt * 16 + arow;
                ldsm4(ah[mt], &sAh[r * PPAD + acol]);
                ldsm4(al[mt], &sAl[r * PPAD + acol]);
            }
            const int bcol = kc * 16 + ((lane >> 3) & 1) * 8;
            const int brow = (lane & 7) + (lane >> 4) * 8;
            {
                const int r = wn + brow;
                uint32_t t[4];
                ldsm4(t, &sBh[r * PPAD + bcol]);
                bh[0][0] = t[0]; bh[0][1] = t[1];
                bh[1][0] = t[2]; bh[1][1] = t[3];
                ldsm4(t, &sBl[r * PPAD + bcol]);
                bl[0][0] = t[0]; bl[0][1] = t[1];
                bl[1][0] = t[2]; bl[1][1] = t[3];
            }
#pragma unroll
            for (int mt = 0; mt < 2; mt++)
#pragma unroll
                for (int np = 0; np < 2; np++) {
                    mma_bf16(acc[mt][np], ah[mt], bh[np]);
                    mma_bf16(acc[mt][np], ah[mt], bl[np]);
                    mma_bf16(acc[mt][np], al[mt], bh[np]);
                }
        }
        __syncthreads();
    }

    const int rb = lane >> 2, cb = (lane & 3) * 2;
#pragma unroll
    for (int mt = 0; mt < 2; mt++)
#pragma unroll
        for (int np = 0; np < 2; np++) {
            const int gm0 = bm + wm + mt * 16 + rb;
            const int gm1 = gm0 + 8;
            const int gn = bn + wn + np * 8 + cb;
            const float b0 = bias[gn], b1 = bias[gn + 1];
            *(float2*)(C + (size_t)gm0 * N + gn) =
                make_float2(acc[mt][np][0] + b0, acc[mt][np][1] + b1);
            *(float2*)(C + (size_t)gm1 * N + gn) =
                make_float2(acc[mt][np][2] + b0, acc[mt][np][3] + b1);
        }
}

__device__ __forceinline__ void attn_phase(
    int b, const __half* __restrict__ fph, const float* __restrict__ hgh,
    const float* __restrict__ ws, const __half* __restrict__ featsh,
    bf16* __restrict__ ctx_h, bf16* __restrict__ ctx_l, char* raw)
{
    AttnSmem* sm = (AttnSmem*)raw;
    const int tid = threadIdx.x;
    const int warp = tid >> 5, lane = tid & 31;

    __syncthreads();
    for (int i = tid; i < NH; i += NTHR) {
        sm->hp[i] = hgh[b * 4 * NH + i];
        sm->ws[i] = ws[i];
    }
    __syncthreads();

    for (int t = warp; t < T_STEPS; t += 8) {
        const __half2* fpr = (const __half2*)(fph + ((size_t)t * NB + b) * NH);
        float sum = 0.0f;
#pragma unroll
        for (int i = 0; i < NH / 64; i++) {
            const int h2 = lane + i * 32;
            const float2 v = __half22float2(fpr[h2]);
            const int h = h2 * 2;
            sum = fmaf(fast_tanh(v.x + sm->hp[h]),     sm->ws[h],     sum);
            sum = fmaf(fast_tanh(v.y + sm->hp[h + 1]), sm->ws[h + 1], sum);
        }
#pragma unroll
        for (int o = 16; o; o >>= 1) sum += __shfl_xor_sync(0xffffffffu, sum, o);
        if (lane == 0) sm->e[t] = sum;
    }
    __syncthreads();

    float v = (tid < T_STEPS) ? sm->e[tid] : -INFINITY;
    float m = v;
#pragma unroll
    for (int o = 16; o; o >>= 1) m = fmaxf(m, __shfl_xor_sync(0xffffffffu, m, o));
    if (lane == 0) sm->rmax[warp] = m;
    __syncthreads();
    float m0 = sm->rmax[0];
#pragma unroll
    for (int w = 1; w < 8; w++) m0 = fmaxf(m0, sm->rmax[w]);
    const float ev = (tid < T_STEPS) ? __expf(v - m0) : 0.0f;
    float s = ev;
#pragma unroll
    for (int o = 16; o; o >>= 1) s += __shfl_xor_sync(0xffffffffu, s, o);
    if (lane == 0) sm->rsum[warp] = s;
    __syncthreads();
    float tot = 0.0f;
#pragma unroll
    for (int w = 0; w < 8; w++) tot += sm->rsum[w];
    if (tid < T_STEPS) sm->e[tid] = ev * __fdividef(1.0f, tot);
    __syncthreads();

    {
        const int c2 = tid;
        float acc0 = 0.0f, acc1 = 0.0f;
        const __half2* base = (const __half2*)(featsh + (size_t)b * NC) + c2;
#pragma unroll 4
        for (int t = 0; t < T_STEPS; t++) {
            const float2 f2 = __half22float2(base[(size_t)t * NB * (NC / 2)]);
            const float a = sm->e[t];
            acc0 = fmaf(a, f2.x, acc0);
            acc1 = fmaf(a, f2.y, acc1);
        }
        const int c = c2 * 2;
        bf16 h0, l0, h1, l1;
        split_bf16(acc0, h0, l0);
        split_bf16(acc1, h1, l1);
        ctx_h[b * NC + c] = h0;  ctx_h[b * NC + c + 1] = h1;
        ctx_l[b * NC + c] = l0;  ctx_l[b * NC + c + 1] = l1;
    }
}

__global__ __launch_bounds__(NTHR, 1) void persistent_steps(
    const __half* __restrict__ fph, const __half* __restrict__ featsh,
    const bf16* __restrict__ Wcat_h, const bf16* __restrict__ Wcat_l,
    const float* __restrict__ bcat,
    const bf16* __restrict__ Wih_h, const bf16* __restrict__ Wih_l,
    const float* __restrict__ b_ih, const float* __restrict__ ws,
    float* __restrict__ hgh, float* __restrict__ gi,
    bf16* __restrict__ ctx_h, bf16* __restrict__ ctx_l,
    float* __restrict__ h, bf16* __restrict__ h_h, bf16* __restrict__ h_l,
    bf16* __restrict__ hs_h, bf16* __restrict__ hs_l)
{
    __shared__ __align__(16) char raw[SMEM_BYTES];
    const int blk = blockIdx.x;
    const int tid = threadIdx.x;
    const int tm = blk & 3, tn = blk >> 2;

    for (int s = 0; s < NL; s++) {
        // A: [hp|gh] = h @ Wcat^T + bcat  (4x32 = 128 tiles of 64x64)
        gemm_phase64(h_h, h_l, Wcat_h, Wcat_l, bcat, hgh,
                     4 * NH, tm * 64, tn * 64, raw);
        gbar(s * 4 + 0);

        // B: attention (2 batches per block)
        attn_phase(blk * 2 + 0, fph, hgh, ws, featsh, ctx_h, ctx_l, raw);
        attn_phase(blk * 2 + 1, fph, hgh, ws, featsh, ctx_h, ctx_l, raw);
        gbar(s * 4 + 1);

        // C: gi = ctx @ Wih^T + b_ih  (4x24 = 96 tiles)
        if (tn < 24)
            gemm_phase64(ctx_h, ctx_l, Wih_h, Wih_l, b_ih, gi,
                         3 * NH, tm * 64, tn * 64, raw);
        gbar(s * 4 + 2);

        // D: GRU gates
        for (int idx = blk * NTHR + tid; idx < NB * NH; idx += NBLK * NTHR) {
            const int b = idx >> 9, hh = idx & (NH - 1);
            const float* gib = gi + b * 3 * NH;
            const float* ghb = hgh + b * 4 * NH + NH;
            const float r = fast_sigmoid(gib[hh]          + ghb[hh]);
            const float z = fast_sigmoid(gib[NH + hh]     + ghb[NH + hh]);
            const float n = fast_tanh   (gib[2 * NH + hh] + r * ghb[2 * NH + hh]);
            const float hnew = (1.0f - z) * n + z * h[idx];
            h[idx] = hnew;
            bf16 hi, lo;
            split_bf16(hnew, hi, lo);
            h_h[idx] = hi;
            h_l[idx] = lo;
            const size_t o = ((size_t)b * NL + s) * NH + hh;
            hs_h[o] = hi;
            hs_l[o] = lo;
        }
        gbar(s * 4 + 3);
    }
}

// ---------- setup helpers ----------------------------------------------------
__global__ void reset_bar_kernel() {
    const int i = threadIdx.x;
    if (i < NSLOTS) g_bar_cnt[i] = 0u;
}
__global__ void zero_h_kernel(float* h, bf16* h_h, bf16* h_l) {
    const int i = blockIdx.x * 256 + threadIdx.x;
    if (i < NB * NH) {
        h[i] = 0.0f;
        h_h[i] = __float2bfloat16(0.0f);
        h_l[i] = __float2bfloat16(0.0f);
    }
}
__global__ void split_kernel(const float* __restrict__ src,
                             bf16* __restrict__ hi, bf16* __restrict__ lo, int n)
{
    const int i = blockIdx.x * 256 + threadIdx.x;
    if (i < n) {
        bf16 h, l;
        split_bf16(src[i], h, l);
        hi[i] = h; lo[i] = l;
    }
}
__global__ void concat_split_kernel(const float* __restrict__ W_h2h,
                                    const float* __restrict__ W_hh,
                                    const float* __restrict__ b_h2h,
                                    const float* __restrict__ b_hh,
                                    bf16* __restrict__ Wh, bf16* __restrict__ Wl,
                                    float* __restrict__ bcat)
{
    const int i = blockIdx.x * 256 + threadIdx.x;
    const int total = 4 * NH * NH;
    if (i < total) {
        const int row = i / NH;
        const float x = (row < NH) ? W_h2h[i] : W_hh[i - NH * NH];
        bf16 h, l;
        split_bf16(x, h, l);
        Wh[i] = h; Wl[i] = l;
    }
    if (i < 4 * NH)
        bcat[i] = (i < NH) ? b_h2h[i] : b_hh[i - NH];
}
__global__ void f2h_kernel(const float* __restrict__ src, __half* __restrict__ dst,
                           int n2)
{
    const int i = blockIdx.x * 256 + threadIdx.x;
    if (i < n2) {
        const float2 v = ((const float2*)src)[i];
        ((__half2*)dst)[i] = __floats2half2_rn(v.x, v.y);
    }
}

// ---------------------------------------------------------------------------
extern "C" void kernel_launch(void* const* d_in, const int* in_sizes, int n_in,
                              void* d_out, int out_size)
{
    const float* feats   = (const float*)d_in[0];
    const float* W_i2h   = (const float*)d_in[2];
    const float* W_h2h   = (const float*)d_in[3];
    const float* b_h2h   = (const float*)d_in[4];
    const float* W_score = (const float*)d_in[5];
    const float* W_ih    = (const float*)d_in[6];
    const float* W_hh    = (const float*)d_in[7];
    const float* b_ih    = (const float*)d_in[8];
    const float* b_hh    = (const float*)d_in[9];
    const float* W_gen   = (const float*)d_in[10];
    const float* b_gen   = (const float*)d_in[11];
    float* out = (float*)d_out;

    bf16 *feats_h = 0, *feats_l = 0, *Wcat_h = 0, *Wcat_l = 0;
    bf16 *Wih_h = 0, *Wih_l = 0, *Wi2h_h = 0, *Wi2h_l = 0;
    bf16 *Wgen_h = 0, *Wgen_l = 0, *ctx_h = 0, *ctx_l = 0;
    bf16 *h_h = 0, *h_l = 0, *hs_h = 0, *hs_l = 0;
    float *bcat = 0, *hgh = 0, *gi = 0, *h = 0;
    __half *fph = 0, *featsh = 0;
    cudaGetSymbolAddress((void**)&feats_h, g_feats_h);
    cudaGetSymbolAddress((void**)&feats_l, g_feats_l);
    cudaGetSymbolAddress((void**)&fph,     g_fph);
    cudaGetSymbolAddress((void**)&featsh,  g_featsh);
    cudaGetSymbolAddress((void**)&Wcat_h,  g_Wcat_h);
    cudaGetSymbolAddress((void**)&Wcat_l,  g_Wcat_l);
    cudaGetSymbolAddress((void**)&bcat,    g_bcat);
    cudaGetSymbolAddress((void**)&Wih_h,   g_Wih_h);
    cudaGetSymbolAddress((void**)&Wih_l,   g_Wih_l);
    cudaGetSymbolAddress((void**)&Wi2h_h,  g_Wi2h_h);
    cudaGetSymbolAddress((void**)&Wi2h_l,  g_Wi2h_l);
    cudaGetSymbolAddress((void**)&Wgen_h,  g_Wgen_h);
    cudaGetSymbolAddress((void**)&Wgen_l,  g_Wgen_l);
    cudaGetSymbolAddress((void**)&hgh,     g_hgh);
    cudaGetSymbolAddress((void**)&gi,      g_gi);
    cudaGetSymbolAddress((void**)&ctx_h,   g_ctx_h);
    cudaGetSymbolAddress((void**)&ctx_l,   g_ctx_l);
    cudaGetSymbolAddress((void**)&h,       g_h);
    cudaGetSymbolAddress((void**)&h_h,     g_h_h);
    cudaGetSymbolAddress((void**)&h_l,     g_h_l);
    cudaGetSymbolAddress((void**)&hs_h,    g_hs_h);
    cudaGetSymbolAddress((void**)&hs_l,    g_hs_l);

    // ---- setup ----
    zero_h_kernel<<<(NB * NH + 255) / 256, 256>>>(h, h_h, h_l);
    {
        const int n = T_STEPS * NB * NC;
        split_kernel<<<(n + 255) / 256, 256>>>(feats, feats_h, feats_l, n);
        f2h_kernel<<<(n / 2 + 255) / 256, 256>>>(feats, featsh, n / 2);
    }
    concat_split_kernel<<<(4 * NH * NH + 255) / 256, 256>>>(
        W_h2h, W_hh, b_h2h, b_hh, Wcat_h, Wcat_l, bcat);
    split_kernel<<<(3 * NH * NC + 255) / 256, 256>>>(W_ih, Wih_h, Wih_l, 3 * NH * NC);
    split_kernel<<<(NH * NC + 255) / 256, 256>>>(W_i2h, Wi2h_h, Wi2h_l, NH * NC);
    split_kernel<<<(NCLS * NH + 255) / 256, 256>>>(W_gen, Wgen_h, Wgen_l, NCLS * NH);

    // feats_proj (fp16 out) = feats @ W_i2h^T
    {
        dim3 grid(NH / 128, (T_STEPS * NB) / 128);
        gemm_bf16split<true><<<grid, 256>>>(feats_h, feats_l, Wi2h_h, Wi2h_l,
                                            nullptr, fph, T_STEPS * NB, NH, KDIM);
    }

    // ---- recurrence: one persistent kernel ----
    reset_bar_kernel<<<1, 128>>>();
    persistent_steps<<<NBLK, NTHR>>>(fph, featsh, Wcat_h, Wcat_l, bcat,
                                     Wih_h, Wih_l, b_ih, W_score,
                                     hgh, gi, ctx_h, ctx_l,
                                     h, h_h, h_l, hs_h, hs_l);

    // ---- generator ----
    {
        dim3 grid((NCLS + 127) / 128, (NB * NL) / 128);
        gemm_bf16split<false><<<grid, 256>>>(hs_h, hs_l, Wgen_h, Wgen_l,
                                             b_gen, out, NB * NL, NCLS, KDIM);
    }
}